// round 3
// baseline (speedup 1.0000x reference)
#include <cuda_runtime.h>

// ---------------------------------------------------------------------------
// Caps2dMatwo fused kernel, v2.
// Shapes: N=2, T0=4 (c), T1=8 (t), H=W=128, PD=AD=4, Z=32, KS=3, ROUTINGS=3.
//
// v2 changes vs v1 (which was LDS/issue bound, L1=52%):
//  - u_hat smem layout [ct][z][pix(+2 pad)] : phase-B float2 stores (pixel
//    pairs), phase-C lane-contiguous scalar loads; all conflict-free.
//  - phase C register-caches all 64 u_hat values per thread: u_hat smem
//    traffic is now write-once / read-once (was read 5x).
//  - phase B: one thread = (ct, pixel-pair); 3-tap windows loaded as two
//    LDS.64 instead of 6 scalar LDS.
// ---------------------------------------------------------------------------

#define SX_SIZE   (4*32*3*36)          // 13824 floats: x tile [c*32+z][3][36]
#define UH_STRIDE 34                   // 32 pixels + 2 pad (even for float2)
#define UH_SIZE   (32*32*UH_STRIDE)    // 34816 floats: [ct][z][pix]
#define SMEM_FLOATS (SX_SIZE + UH_SIZE + 288 + 512 + 512 + 128 + 512*5)
#define SMEM_BYTES (SMEM_FLOATS * 4)   // 210,560 bytes

__device__ __forceinline__ float sigf(float v) {
    return 1.0f / (1.0f + __expf(-v));
}

__global__ void __launch_bounds__(512, 1)
caps_kernel(const float* __restrict__ x,     // (2,4,32,128,128)
            const float* __restrict__ Wc,    // (4,3,3,1,8)  flat 288
            const float* __restrict__ Wp,    // (4,16,8)     flat 512
            const float* __restrict__ Wa,    // (4,16,8)     flat 512
            const float* __restrict__ ba,    // (4,8)        flat 32
            float* __restrict__ out)         // (2,8,32,128,128)
{
    extern __shared__ float sm[];
    float* s_x  = sm;                    // 13824
    float* s_uh = s_x + SX_SIZE;         // [ct*32+z]*34 + pix
    float* s_wc = s_uh + UH_SIZE;        // 288  [c][kh*3+kw][t1]
    float* s_mp = s_wc + 288;            // 512  [c][t][j][k] normalized
    float* s_ma = s_mp + 512;            // 512  [c][t][j][k]
    float* s_bb = s_ma + 512;            // 128  [c][t][k] = b_app*sum_j mapp
    float* s_ex = s_bb + 128;            // 2560 exchange [tid*5]

    const int tid = threadIdx.x;
    const int w0  = blockIdx.x * 32;
    const int h   = blockIdx.y;
    const int n   = blockIdx.z;

    // ---- weights into smem ----
    if (tid < 288) s_wc[tid] = Wc[tid];
    s_ma[tid] = Wa[tid];
    if (tid >= 288 && tid < 416) {
        int q = tid - 288;                       // one (c,t,k) each
        int c = q >> 5, t = (q >> 2) & 7, k = q & 3;
        const float* wpp = Wp + c*128 + t*16 + k;
        float m0 = wpp[0], m1 = wpp[4], m2 = wpp[8], m3 = wpp[12];
        float inv = rsqrtf(fmaxf(m0*m0 + m1*m1 + m2*m2 + m3*m3, 1e-12f));
        float* d = s_mp + (c*8 + t)*16 + k;
        d[0] = m0*inv; d[4] = m1*inv; d[8] = m2*inv; d[12] = m3*inv;
        const float* wap = Wa + c*128 + t*16 + k;
        s_bb[(c*8 + t)*4 + k] = ba[c*8 + t] * (wap[0] + wap[4] + wap[8] + wap[12]);
    }

    // ---- x halo tile load (rows h-1..h+1, cols w0-1..w0+32, zero-padded) ----
    for (int idx = tid; idx < 4*32*3*34; idx += 512) {
        int col  = idx % 34;
        int rest = idx / 34;
        int r3   = rest % 3;
        int cz   = rest / 3;                      // c*32+z
        int gr = h + r3 - 1;
        int gc = w0 + col - 1;
        float v = 0.0f;
        if (gr >= 0 && gr < 128 && gc >= 0 && gc < 128)
            v = x[(((long)n*128 + cz)*128 + gr)*128 + gc];
        s_x[(cz*3 + r3)*36 + col] = v;
    }
    __syncthreads();

    // ---- Phase B: conv + u_hat. One thread = (ct, pixel pair q). ----
    {
        const int ct = tid >> 4;                  // 0..31 (2 per warp)
        const int q  = tid & 15;                  // pixel pair: pix = 2q, 2q+1
        const int c = ct >> 3, t = ct & 7;
        const int zb  = (t & 1) << 4;
        const int t1p = t >> 1;                   // pos channel; app = t1p+4

        float wp9[9], wa9[9];
#pragma unroll
        for (int p = 0; p < 9; ++p) {
            wp9[p] = s_wc[(c*9 + p)*8 + t1p];
            wa9[p] = s_wc[(c*9 + p)*8 + t1p + 4];
        }
        const float wcd0 = (float)(w0 + 2*q)     * (1.0f/128.0f);
        const float wcd1 = (float)(w0 + 2*q + 1) * (1.0f/128.0f);
        const float hcd  = (float)h * (1.0f/128.0f);
        const float* mp = s_mp + ct*16;
        const float* ma = s_ma + ct*16;
        const float* bb = s_bb + ct*4;
        float* ub = s_uh + ct*32*UH_STRIDE + 2*q;

#pragma unroll
        for (int i = 0; i < 4; ++i) {
            float cp0[4], cp1[4], ca0[4], ca1[4];
#pragma unroll
            for (int mm = 0; mm < 4; ++mm) {
                const float* xb = s_x + ((c*32 + zb + i*4 + mm)*3)*36 + 2*q;
                float ap0 = 0.f, ap1 = 0.f, aa0 = 0.f, aa1 = 0.f;
#pragma unroll
                for (int kh = 0; kh < 3; ++kh) {
                    float2 d0 = *(const float2*)(xb + kh*36);
                    float2 d1 = *(const float2*)(xb + kh*36 + 2);
                    float wP0 = wp9[kh*3], wP1 = wp9[kh*3+1], wP2 = wp9[kh*3+2];
                    float wA0 = wa9[kh*3], wA1 = wa9[kh*3+1], wA2 = wa9[kh*3+2];
                    ap0 = fmaf(d0.x, wP0, ap0); ap0 = fmaf(d0.y, wP1, ap0); ap0 = fmaf(d1.x, wP2, ap0);
                    ap1 = fmaf(d0.y, wP0, ap1); ap1 = fmaf(d1.x, wP1, ap1); ap1 = fmaf(d1.y, wP2, ap1);
                    aa0 = fmaf(d0.x, wA0, aa0); aa0 = fmaf(d0.y, wA1, aa0); aa0 = fmaf(d1.x, wA2, aa0);
                    aa1 = fmaf(d0.y, wA0, aa1); aa1 = fmaf(d1.x, wA1, aa1); aa1 = fmaf(d1.y, wA2, aa1);
                }
                cp0[mm] = ap0; cp1[mm] = ap1; ca0[mm] = aa0; ca1[mm] = aa1;
            }
#pragma unroll
            for (int k = 0; k < 4; ++k) {
                float u0 = cp0[0]*mp[k] + cp0[1]*mp[4+k] + cp0[2]*mp[8+k] + cp0[3]*mp[12+k];
                float u1 = cp1[0]*mp[k] + cp1[1]*mp[4+k] + cp1[2]*mp[8+k] + cp1[3]*mp[12+k];
                if (k == 0) { u0 += cp0[3]*wcd0; u1 += cp1[3]*wcd1; }
                if (k == 1) { u0 += cp0[3]*hcd;  u1 += cp1[3]*hcd;  }
                *(float2*)(ub + (i*4 + k)*UH_STRIDE) = make_float2(u0, u1);
                float v0 = bb[k] + ca0[0]*ma[k] + ca0[1]*ma[4+k] + ca0[2]*ma[8+k] + ca0[3]*ma[12+k];
                float v1 = bb[k] + ca1[0]*ma[k] + ca1[1]*ma[4+k] + ca1[2]*ma[8+k] + ca1[3]*ma[12+k];
                *(float2*)(ub + (16 + i*4 + k)*UH_STRIDE) = make_float2(v0, v1);
            }
        }
    }
    __syncthreads();

    // ---- Phase C: routing, thread = (s=pos/app, t, pix); u_hat in regs ----
    {
        const int s   = tid >> 8;                 // warp-uniform
        const int t   = (tid >> 5) & 7;           // warp-uniform
        const int pix = tid & 31;

        // load u[c][zl], z = s*16+zl  (write-once / read-once smem traffic)
        float u0[16], u1[16], u2[16], u3[16];
        {
            const float* b0 = s_uh + ((0*8 + t)*32 + s*16)*UH_STRIDE + pix;
            const float* b1 = s_uh + ((1*8 + t)*32 + s*16)*UH_STRIDE + pix;
            const float* b2 = s_uh + ((2*8 + t)*32 + s*16)*UH_STRIDE + pix;
            const float* b3 = s_uh + ((3*8 + t)*32 + s*16)*UH_STRIDE + pix;
#pragma unroll
            for (int zl = 0; zl < 16; ++zl) {
                u0[zl] = b0[zl*UH_STRIDE];
                u1[zl] = b1[zl*UH_STRIDE];
                u2[zl] = b2[zl*UH_STRIDE];
                u3[zl] = b3[zl*UH_STRIDE];
            }
        }

        float* ex        = s_ex + tid*5;
        const float* exo = s_ex + (tid ^ 256)*5;

        float b0 = 0.f, b1 = 0.f, b2 = 0.f, b3 = 0.f;
        float p[16];

#pragma unroll
        for (int it = 0; it < 3; ++it) {
            float r0 = sigf(b0), r1 = sigf(b1), r2 = sigf(b2), r3 = sigf(b3);
#pragma unroll
            for (int zl = 0; zl < 16; ++zl)
                p[zl] = u0[zl]*r0 + u1[zl]*r1 + u2[zl]*r2 + u3[zl]*r3;
            if (s == 0) {                         // psquash over z<16
                float m = 0.f;
#pragma unroll
                for (int zl = 0; zl < 16; ++zl) m = fmaxf(m, fabsf(p[zl]));
                float inv = 1.0f / m;
#pragma unroll
                for (int zl = 0; zl < 16; ++zl) p[zl] *= inv;
            } else {                              // matwo squash over z>=16
                float sq = 0.f;
#pragma unroll
                for (int zl = 0; zl < 16; ++zl) sq = fmaf(p[zl], p[zl], sq);
                float sc = sq / (1.0f + sq) * rsqrtf(sq + 1e-9f);
#pragma unroll
                for (int zl = 0; zl < 16; ++zl) p[zl] *= sc;
            }
            if (it == 2) break;                   // last pass: p holds v

            float q0 = 0.f, q1 = 0.f, q2 = 0.f, q3 = 0.f;
#pragma unroll
            for (int zl = 0; zl < 16; ++zl) {
                q0 = fmaf(u0[zl], p[zl], q0);
                q1 = fmaf(u1[zl], p[zl], q1);
                q2 = fmaf(u2[zl], p[zl], q2);
                q3 = fmaf(u3[zl], p[zl], q3);
            }
            __syncthreads();                      // WAR guard on s_ex
            ex[0] = q0; ex[1] = q1; ex[2] = q2; ex[3] = q3;
            __syncthreads();
            b0 += q0 * exo[0];
            b1 += q1 * exo[1];
            b2 += q2 * exo[2];
            b3 += q3 * exo[3];
        }

        // out[n][t][z][h][w]
        float* ob = out + ((long)(n*8 + t)*32 + s*16)*16384 + h*128 + w0 + pix;
#pragma unroll
        for (int zl = 0; zl < 16; ++zl)
            ob[(long)zl*16384] = p[zl];
    }
}

extern "C" void kernel_launch(void* const* d_in, const int* in_sizes, int n_in,
                              void* d_out, int out_size)
{
    const float* x  = (const float*)d_in[0];
    const float* Wc = (const float*)d_in[1];
    const float* Wp = (const float*)d_in[2];
    const float* Wa = (const float*)d_in[3];
    const float* ba = (const float*)d_in[4];
    float* out = (float*)d_out;

    cudaFuncSetAttribute(caps_kernel,
                         cudaFuncAttributeMaxDynamicSharedMemorySize,
                         SMEM_BYTES);

    dim3 grid(4, 128, 2);   // (w/32, h, n)
    caps_kernel<<<grid, 512, SMEM_BYTES>>>(x, Wc, Wp, Wa, ba, out);
}

// round 6
// speedup vs baseline: 1.3418x; 1.3418x over previous
#include <cuda_runtime.h>

// ---------------------------------------------------------------------------
// Caps2dMatwo fused kernel, v3 = v1 (94.7us) + register-cached phase C ONLY.
// Shapes: N=2, T0=4 (c), T1=8 (t), H=W=128, PD=AD=4, Z=32, KS=3, ROUTINGS=3.
//
//   conv out u[c, t1', z']  (t1' in 0..7, z' in 0..31)
//   u_pos_val(c,t,i,j) = u[c, t/2,     16*(t&1) + i*4 + j]
//   u_app_val(c,t,i,j) = u[c, 4 + t/2, 16*(t&1) + i*4 + j]
//   mpos[c,t,j,k] = Wp_flat[c*128 + t*16 + j*4 + k], column-normalized over j
//   u_hat[z=i*4+k,    c,t] = sum_j u_pos*mposn + u_pos(j=3)*(k==0? w/W : k==1? h/H : 0)
//   u_hat[z=16+i*4+k, c,t] = b_app[c,t]*sum_j mapp[j,k] + sum_j u_app*mapp[j,k]
// Routing per (pixel, t): p[z]=sum_c uhat*r[c]; psquash (z<16) / matwo (z>=16);
// rout[c]=(sum_{z<16} uhat*v)*(sum_{z>=16} uhat*v); b+=rout.
// ---------------------------------------------------------------------------

#define SX_SIZE   (4*32*3*36)          // 13824 floats: x tile [c][z][3][36]
#define UH_STRIDE 1033                 // 32 z * 32 ct + 9 pad (9 mod 32, coprime)
#define UH_SIZE   (32*UH_STRIDE)       // 33056 floats
#define SMEM_FLOATS (SX_SIZE + UH_SIZE + 288 + 512 + 512 + 128 + 512*5)
#define SMEM_BYTES (SMEM_FLOATS * 4)   // 203,520 bytes

__device__ __forceinline__ float sigf(float v) {
    return 1.0f / (1.0f + __expf(-v));
}

__global__ void __launch_bounds__(512, 1)
caps_kernel(const float* __restrict__ x,     // (2,4,32,128,128)
            const float* __restrict__ Wc,    // (4,3,3,1,8)  flat 288
            const float* __restrict__ Wp,    // (4,16,8)     flat 512
            const float* __restrict__ Wa,    // (4,16,8)     flat 512
            const float* __restrict__ ba,    // (4,8)        flat 32
            float* __restrict__ out)         // (2,8,32,128,128)
{
    extern __shared__ float sm[];
    float* s_x  = sm;                    // 13824
    float* s_uh = s_x + SX_SIZE;         // 33056, [pix]*1033 + z*32 + ct
    float* s_wc = s_uh + UH_SIZE;        // 288  [c][kh*3+kw][t1]
    float* s_mp = s_wc + 288;            // 512  [c][t][j][k] normalized
    float* s_ma = s_mp + 512;            // 512  [c][t][j][k]
    float* s_bb = s_ma + 512;            // 128  [c][t][k]  = b_app*sum_j mapp
    float* s_ex = s_bb + 128;            // 2560 exchange [tid][5-pad]

    const int tid = threadIdx.x;
    const int w0  = blockIdx.x * 32;
    const int h   = blockIdx.y;
    const int n   = blockIdx.z;

    // ---- weights into smem ----
    if (tid < 288) s_wc[tid] = Wc[tid];
    if (tid < 512) s_ma[tid] = Wa[tid];
    if (tid >= 288 && tid < 416) {
        int q = tid - 288;                       // one (c,t,k) each
        int c = q >> 5, t = (q >> 2) & 7, k = q & 3;
        const float* wpp = Wp + c*128 + t*16 + k;
        float m0 = wpp[0], m1 = wpp[4], m2 = wpp[8], m3 = wpp[12];
        float inv = rsqrtf(fmaxf(m0*m0 + m1*m1 + m2*m2 + m3*m3, 1e-12f));
        float* d = s_mp + (c*8 + t)*16 + k;
        d[0] = m0*inv; d[4] = m1*inv; d[8] = m2*inv; d[12] = m3*inv;
        const float* wap = Wa + c*128 + t*16 + k;
        s_bb[(c*8 + t)*4 + k] = ba[c*8 + t] * (wap[0] + wap[4] + wap[8] + wap[12]);
    }

    // ---- x halo tile load (rows h-1..h+1, cols w0-1..w0+32, zero-padded) ----
    for (int idx = tid; idx < 4*32*3*34; idx += 512) {
        int col  = idx % 34;
        int rest = idx / 34;
        int r3   = rest % 3;
        int cz   = rest / 3;                      // c*32+z
        int gr = h + r3 - 1;
        int gc = w0 + col - 1;
        float v = 0.0f;
        if (gr >= 0 && gr < 128 && gc >= 0 && gc < 128)
            v = x[(((long)n*128 + cz)*128 + gr)*128 + gc];
        s_x[(cz*3 + r3)*36 + col] = v;
    }
    __syncthreads();

    // ---- Phase B: conv + u_hat, 2 units per thread, unit = ct*32 + pix ----
#pragma unroll
    for (int uu = 0; uu < 2; ++uu) {
        int unit = tid + uu*512;
        int ct  = unit >> 5;                      // warp-uniform
        int pix = unit & 31;
        int c = ct >> 3, t = ct & 7;
        int zb  = (t & 1) << 4;
        int t1p = t >> 1;                         // pos channel; app = t1p+4

        float wp9[9], wa9[9];
#pragma unroll
        for (int p = 0; p < 9; ++p) {
            wp9[p] = s_wc[(c*9 + p)*8 + t1p];
            wa9[p] = s_wc[(c*9 + p)*8 + t1p + 4];
        }
        float cp[16], ca[16];
#pragma unroll
        for (int m = 0; m < 16; ++m) {
            const float* xb = s_x + ((c*32 + zb + m)*3)*36 + pix;
            float ap = 0.f, aa = 0.f;
#pragma unroll
            for (int kh = 0; kh < 3; ++kh)
#pragma unroll
                for (int kw = 0; kw < 3; ++kw) {
                    float xv = xb[kh*36 + kw];
                    ap = fmaf(xv, wp9[kh*3 + kw], ap);
                    aa = fmaf(xv, wa9[kh*3 + kw], aa);
                }
            cp[m] = ap; ca[m] = aa;
        }

        float wcd = (float)(w0 + pix) * (1.0f/128.0f);
        float hcd = (float)h * (1.0f/128.0f);
        float* ub = s_uh + pix*UH_STRIDE + ct;
        const float* mp = s_mp + (c*8 + t)*16;
        const float* ma = s_ma + (c*8 + t)*16;
        const float* bb = s_bb + (c*8 + t)*4;
#pragma unroll
        for (int i = 0; i < 4; ++i) {
            float p0 = cp[4*i+0], p1 = cp[4*i+1], p2 = cp[4*i+2], p3 = cp[4*i+3];
            float a0 = ca[4*i+0], a1 = ca[4*i+1], a2 = ca[4*i+2], a3 = ca[4*i+3];
#pragma unroll
            for (int k = 0; k < 4; ++k) {
                float u = p0*mp[k] + p1*mp[4+k] + p2*mp[8+k] + p3*mp[12+k];
                if (k == 0) u += p3 * wcd;
                if (k == 1) u += p3 * hcd;
                ub[(i*4 + k)*32] = u;
                float va = bb[k] + a0*ma[k] + a1*ma[4+k] + a2*ma[8+k] + a3*ma[12+k];
                ub[(16 + i*4 + k)*32] = va;
            }
        }
    }
    __syncthreads();

    // ---- Phase C: routing, thread = (s=pos/app, t, pix); u_hat in regs ----
    {
        const int s   = tid >> 8;                 // warp-uniform
        const int t   = (tid >> 5) & 7;           // warp-uniform
        const int pix = tid & 31;
        const float* ub = s_uh + pix*UH_STRIDE + s*512 + t;   // [zl*32 + c*8]

        // one-time read of this thread's 64 u_hat values (was read 5x in v1)
        float u0[16], u1[16], u2[16], u3[16];
#pragma unroll
        for (int zl = 0; zl < 16; ++zl) {
            const float* u = ub + zl*32;
            u0[zl] = u[0]; u1[zl] = u[8]; u2[zl] = u[16]; u3[zl] = u[24];
        }

        float* ex        = s_ex + tid*5;
        const float* exo = s_ex + (tid ^ 256)*5;

        float b0 = 0.f, b1 = 0.f, b2 = 0.f, b3 = 0.f;
        float p[16];

#pragma unroll
        for (int it = 0; it < 3; ++it) {
            float r0 = sigf(b0), r1 = sigf(b1), r2 = sigf(b2), r3 = sigf(b3);
#pragma unroll
            for (int zl = 0; zl < 16; ++zl)
                p[zl] = u0[zl]*r0 + u1[zl]*r1 + u2[zl]*r2 + u3[zl]*r3;
            if (s == 0) {                         // psquash over z<16
                float m = 0.f;
#pragma unroll
                for (int zl = 0; zl < 16; ++zl) m = fmaxf(m, fabsf(p[zl]));
                float inv = 1.0f / m;
#pragma unroll
                for (int zl = 0; zl < 16; ++zl) p[zl] *= inv;
            } else {                              // matwo squash over z>=16
                float sq = 0.f;
#pragma unroll
                for (int zl = 0; zl < 16; ++zl) sq = fmaf(p[zl], p[zl], sq);
                float sc = sq / (1.0f + sq) * rsqrtf(sq + 1e-9f);
#pragma unroll
                for (int zl = 0; zl < 16; ++zl) p[zl] *= sc;
            }
            if (it == 2) break;                   // last pass: p holds v

            float q0 = 0.f, q1 = 0.f, q2 = 0.f, q3 = 0.f;
#pragma unroll
            for (int zl = 0; zl < 16; ++zl) {
                q0 = fmaf(u0[zl], p[zl], q0);
                q1 = fmaf(u1[zl], p[zl], q1);
                q2 = fmaf(u2[zl], p[zl], q2);
                q3 = fmaf(u3[zl], p[zl], q3);
            }
            __syncthreads();                      // WAR guard on s_ex
            ex[0] = q0; ex[1] = q1; ex[2] = q2; ex[3] = q3;
            __syncthreads();
            b0 += q0 * exo[0];
            b1 += q1 * exo[1];
            b2 += q2 * exo[2];
            b3 += q3 * exo[3];
        }

        // out[n][t][z][h][w]
        float* ob = out + ((long)(n*8 + t)*32 + s*16)*16384 + h*128 + w0 + pix;
#pragma unroll
        for (int zl = 0; zl < 16; ++zl)
            ob[(long)zl*16384] = p[zl];
    }
}

extern "C" void kernel_launch(void* const* d_in, const int* in_sizes, int n_in,
                              void* d_out, int out_size)
{
    const float* x  = (const float*)d_in[0];
    const float* Wc = (const float*)d_in[1];
    const float* Wp = (const float*)d_in[2];
    const float* Wa = (const float*)d_in[3];
    const float* ba = (const float*)d_in[4];
    float* out = (float*)d_out;

    cudaFuncSetAttribute(caps_kernel,
                         cudaFuncAttributeMaxDynamicSharedMemorySize,
                         SMEM_BYTES);

    dim3 grid(4, 128, 2);   // (w/32, h, n)
    caps_kernel<<<grid, 512, SMEM_BYTES>>>(x, Wc, Wp, Wa, ba, out);
}

// round 7
// speedup vs baseline: 1.7807x; 1.3271x over previous
#include <cuda_runtime.h>

// ---------------------------------------------------------------------------
// Caps2dMatwo fused kernel, v4.
// Shapes: N=2, T0=4 (c), T1=8 (t1'), H=W=128, PD=AD=4, Z=32, KS=3, ROUTINGS=3.
//
// v4 vs v3 (90.6us, phase-B LDS/issue bound):
//  - Phase B computes conv ONLY, one x-window feeds all 8 channels
//    (72 FMA per 9 LDS instead of 18 per 9).  Conv staged to smem
//    [c][ch][z][pix] (replaces the u_hat buffer, same footprint).
//  - Phase C reads 64 conv values once and performs the 4x4 pos/app
//    matmuls in registers (mp/ma broadcast from smem), then routes.
// ---------------------------------------------------------------------------

#define SX_SIZE   (4*32*3*36)          // 13824 floats: x tile [c*32+z][3][36]
#define CV_SIZE   (4*8*32*32)          // 32768 floats: conv [c][ch][z][pix]
#define SMEM_FLOATS (SX_SIZE + CV_SIZE + 288 + 512 + 512 + 128 + 512*5)
#define SMEM_BYTES (SMEM_FLOATS * 4)   // 202,368 bytes

__device__ __forceinline__ float sigf(float v) {
    return 1.0f / (1.0f + __expf(-v));
}

__global__ void __launch_bounds__(512, 1)
caps_kernel(const float* __restrict__ x,     // (2,4,32,128,128)
            const float* __restrict__ Wc,    // (4,3,3,1,8)  flat 288
            const float* __restrict__ Wp,    // (4,16,8)     flat 512
            const float* __restrict__ Wa,    // (4,16,8)     flat 512
            const float* __restrict__ ba,    // (4,8)        flat 32
            float* __restrict__ out)         // (2,8,32,128,128)
{
    extern __shared__ float sm[];
    float* s_x  = sm;                    // 13824
    float* s_cv = s_x + SX_SIZE;         // 32768: [(c*8+ch)*32+z]*32 + pix
    float* s_wc = s_cv + CV_SIZE;        // 288  [c][kh*3+kw][t1]
    float* s_mp = s_wc + 288;            // 512  [c][t][j][k] normalized
    float* s_ma = s_mp + 512;            // 512  [c][t][j][k]
    float* s_bb = s_ma + 512;            // 128  [c][t][k] = b_app*sum_j mapp
    float* s_ex = s_bb + 128;            // 2560 exchange [tid*5]

    const int tid = threadIdx.x;
    const int w0  = blockIdx.x * 32;
    const int h   = blockIdx.y;
    const int n   = blockIdx.z;

    // ---- weights into smem ----
    if (tid < 288) s_wc[tid] = Wc[tid];
    s_ma[tid] = Wa[tid];
    if (tid >= 288 && tid < 416) {
        int q = tid - 288;                       // one (c,t,k) each
        int c = q >> 5, t = (q >> 2) & 7, k = q & 3;
        const float* wpp = Wp + c*128 + t*16 + k;
        float m0 = wpp[0], m1 = wpp[4], m2 = wpp[8], m3 = wpp[12];
        float inv = rsqrtf(fmaxf(m0*m0 + m1*m1 + m2*m2 + m3*m3, 1e-12f));
        float* d = s_mp + (c*8 + t)*16 + k;
        d[0] = m0*inv; d[4] = m1*inv; d[8] = m2*inv; d[12] = m3*inv;
        const float* wap = Wa + c*128 + t*16 + k;
        s_bb[(c*8 + t)*4 + k] = ba[c*8 + t] * (wap[0] + wap[4] + wap[8] + wap[12]);
    }

    // ---- x halo tile load (rows h-1..h+1, cols w0-1..w0+32, zero-padded) ----
    for (int idx = tid; idx < 4*32*3*34; idx += 512) {
        int col  = idx % 34;
        int rest = idx / 34;
        int r3   = rest % 3;
        int cz   = rest / 3;                      // c*32+z
        int gr = h + r3 - 1;
        int gc = w0 + col - 1;
        float v = 0.0f;
        if (gr >= 0 && gr < 128 && gc >= 0 && gc < 128)
            v = x[(((long)n*128 + cz)*128 + gr)*128 + gc];
        s_x[(cz*3 + r3)*36 + col] = v;
    }
    __syncthreads();

    // ---- Phase B: conv only. thread = (c, z-octet, pix). ----
    {
        const int c   = tid >> 7;                 // 0..3 (warp-uniform)
        const int zq  = (tid >> 5) & 3;           // 0..3 (warp-uniform)
        const int pix = tid & 31;

        // 72 conv weights for this c (warp-broadcast loads)
        float w9[9][8];
#pragma unroll
        for (int p = 0; p < 9; ++p)
#pragma unroll
            for (int ch = 0; ch < 8; ++ch)
                w9[p][ch] = s_wc[(c*9 + p)*8 + ch];

#pragma unroll
        for (int zz = 0; zz < 8; ++zz) {
            const int z = zq*8 + zz;
            const float* xb = s_x + ((c*32 + z)*3)*36 + pix;
            float xv[9];
#pragma unroll
            for (int kh = 0; kh < 3; ++kh) {
                xv[kh*3+0] = xb[kh*36 + 0];
                xv[kh*3+1] = xb[kh*36 + 1];
                xv[kh*3+2] = xb[kh*36 + 2];
            }
            float acc[8] = {0,0,0,0,0,0,0,0};
#pragma unroll
            for (int p = 0; p < 9; ++p)
#pragma unroll
                for (int ch = 0; ch < 8; ++ch)
                    acc[ch] = fmaf(xv[p], w9[p][ch], acc[ch]);
            float* dst = s_cv + ((c*8)*32 + z)*32 + pix;
#pragma unroll
            for (int ch = 0; ch < 8; ++ch)
                dst[ch*1024] = acc[ch];           // 32*32 = 1024 stride
        }
    }
    __syncthreads();

    // ---- Phase C: u_hat matmul in regs + routing. thread = (s, t, pix) ----
    {
        const int s   = tid >> 8;                 // warp-uniform
        const int t   = (tid >> 5) & 7;           // warp-uniform
        const int pix = tid & 31;
        const int t1  = (t >> 1) + (s ? 4 : 0);   // conv channel
        const int zb  = (t & 1) << 4;

        float u[4][16];

        if (s == 0) {
            const float wcd = (float)(w0 + pix) * (1.0f/128.0f);
            const float hcd = (float)h * (1.0f/128.0f);
#pragma unroll
            for (int c = 0; c < 4; ++c) {
                const float* cb = s_cv + ((c*8 + t1)*32 + zb)*32 + pix;
                const float* mp = s_mp + (c*8 + t)*16;
#pragma unroll
                for (int i = 0; i < 4; ++i) {
                    float p0 = cb[(i*4+0)*32], p1 = cb[(i*4+1)*32];
                    float p2 = cb[(i*4+2)*32], p3 = cb[(i*4+3)*32];
#pragma unroll
                    for (int k = 0; k < 4; ++k) {
                        float uv = p0*mp[k] + p1*mp[4+k] + p2*mp[8+k] + p3*mp[12+k];
                        if (k == 0) uv += p3 * wcd;
                        if (k == 1) uv += p3 * hcd;
                        u[c][i*4+k] = uv;
                    }
                }
            }
        } else {
#pragma unroll
            for (int c = 0; c < 4; ++c) {
                const float* cb = s_cv + ((c*8 + t1)*32 + zb)*32 + pix;
                const float* ma = s_ma + (c*8 + t)*16;
                const float* bb = s_bb + (c*8 + t)*4;
#pragma unroll
                for (int i = 0; i < 4; ++i) {
                    float a0 = cb[(i*4+0)*32], a1 = cb[(i*4+1)*32];
                    float a2 = cb[(i*4+2)*32], a3 = cb[(i*4+3)*32];
#pragma unroll
                    for (int k = 0; k < 4; ++k)
                        u[c][i*4+k] = bb[k] + a0*ma[k] + a1*ma[4+k]
                                            + a2*ma[8+k] + a3*ma[12+k];
                }
            }
        }

        float* ex        = s_ex + tid*5;
        const float* exo = s_ex + (tid ^ 256)*5;

        float b0 = 0.f, b1 = 0.f, b2 = 0.f, b3 = 0.f;
        float p[16];

#pragma unroll
        for (int it = 0; it < 3; ++it) {
            float r0 = sigf(b0), r1 = sigf(b1), r2 = sigf(b2), r3 = sigf(b3);
#pragma unroll
            for (int zl = 0; zl < 16; ++zl)
                p[zl] = u[0][zl]*r0 + u[1][zl]*r1 + u[2][zl]*r2 + u[3][zl]*r3;
            if (s == 0) {                         // psquash over z<16
                float m = 0.f;
#pragma unroll
                for (int zl = 0; zl < 16; ++zl) m = fmaxf(m, fabsf(p[zl]));
                float inv = 1.0f / m;
#pragma unroll
                for (int zl = 0; zl < 16; ++zl) p[zl] *= inv;
            } else {                              // matwo squash over z>=16
                float sq = 0.f;
#pragma unroll
                for (int zl = 0; zl < 16; ++zl) sq = fmaf(p[zl], p[zl], sq);
                float sc = sq / (1.0f + sq) * rsqrtf(sq + 1e-9f);
#pragma unroll
                for (int zl = 0; zl < 16; ++zl) p[zl] *= sc;
            }
            if (it == 2) break;                   // last pass: p holds v

            float q0 = 0.f, q1 = 0.f, q2 = 0.f, q3 = 0.f;
#pragma unroll
            for (int zl = 0; zl < 16; ++zl) {
                q0 = fmaf(u[0][zl], p[zl], q0);
                q1 = fmaf(u[1][zl], p[zl], q1);
                q2 = fmaf(u[2][zl], p[zl], q2);
                q3 = fmaf(u[3][zl], p[zl], q3);
            }
            __syncthreads();                      // WAR guard on s_ex
            ex[0] = q0; ex[1] = q1; ex[2] = q2; ex[3] = q3;
            __syncthreads();
            b0 += q0 * exo[0];
            b1 += q1 * exo[1];
            b2 += q2 * exo[2];
            b3 += q3 * exo[3];
        }

        // out[n][t][z][h][w]
        float* ob = out + ((long)(n*8 + t)*32 + s*16)*16384 + h*128 + w0 + pix;
#pragma unroll
        for (int zl = 0; zl < 16; ++zl)
            ob[(long)zl*16384] = p[zl];
    }
}

extern "C" void kernel_launch(void* const* d_in, const int* in_sizes, int n_in,
                              void* d_out, int out_size)
{
    const float* x  = (const float*)d_in[0];
    const float* Wc = (const float*)d_in[1];
    const float* Wp = (const float*)d_in[2];
    const float* Wa = (const float*)d_in[3];
    const float* ba = (const float*)d_in[4];
    float* out = (float*)d_out;

    cudaFuncSetAttribute(caps_kernel,
                         cudaFuncAttributeMaxDynamicSharedMemorySize,
                         SMEM_BYTES);

    dim3 grid(4, 128, 2);   // (w/32, h, n)
    caps_kernel<<<grid, 512, SMEM_BYTES>>>(x, Wc, Wp, Wa, ba, out);
}

// round 8
// speedup vs baseline: 2.2619x; 1.2702x over previous
#include <cuda_runtime.h>

// ---------------------------------------------------------------------------
// Caps2dMatwo fused kernel, v5.
// Shapes: N=2, T0=4 (c), T1=8, H=W=128, PD=AD=4, Z=32, KS=3, ROUTINGS=3.
//
// v5 vs v4 (68.3us, issue/alu bound):
//  - conv buffer re-laid out z-contiguous [cch][pix][z] (pix stride 36):
//    phase B writes 16 STS.128 (was 64 STS.32), phase C reads 16 LDS.128
//    (was 64 LDS.32); both conflict-free, 16B-aligned.
//  - x halo tile loader: float4 LDG/STS with uniform row predicates,
//    no div/mod.
//  - routing exchange: float4 + double-buffered -> 2 barriers, 1 op/dir.
// ---------------------------------------------------------------------------

#define SX_STRIDE 40                   // 34 used cols at idx 3..36, f4-aligned
#define SX_SIZE   (4*32*3*SX_STRIDE)   // 15360 floats
#define CV_PSTR   36                   // z stride pad: mult of 4, odd*4 banks
#define CV_SIZE   (32*32*CV_PSTR)      // 36864 floats: [(c*8+ch)*32+pix]*36+z
#define EX_SIZE   (2*512*4)            // 4096: two float4 buffers
#define SMEM_FLOATS (SX_SIZE + CV_SIZE + 288 + 512 + 512 + 128 + EX_SIZE)
#define SMEM_BYTES (SMEM_FLOATS * 4)   // 231,040 bytes (<= 232,448 opt-in)

__device__ __forceinline__ float sigf(float v) {
    return 1.0f / (1.0f + __expf(-v));
}

__global__ void __launch_bounds__(512, 1)
caps_kernel(const float* __restrict__ x,     // (2,4,32,128,128)
            const float* __restrict__ Wc,    // (4,3,3,1,8)  flat 288
            const float* __restrict__ Wp,    // (4,16,8)     flat 512
            const float* __restrict__ Wa,    // (4,16,8)     flat 512
            const float* __restrict__ ba,    // (4,8)        flat 32
            float* __restrict__ out)         // (2,8,32,128,128)
{
    extern __shared__ float sm[];
    float* s_x  = sm;                    // 15360
    float* s_cv = s_x + SX_SIZE;         // 36864
    float* s_wc = s_cv + CV_SIZE;        // 288  [c][kh*3+kw][t1]
    float* s_mp = s_wc + 288;            // 512  [c][t][j][k] normalized
    float* s_ma = s_mp + 512;            // 512  [c][t][j][k]
    float* s_bb = s_ma + 512;            // 128  [c][t][k] = b_app*sum_j mapp
    float* s_ex = s_bb + 128;            // 4096 exchange, 2 x float4[512]

    const int tid = threadIdx.x;
    const int w0  = blockIdx.x * 32;
    const int h   = blockIdx.y;
    const int n   = blockIdx.z;

    // ---- weights into smem ----
    if (tid < 288) s_wc[tid] = Wc[tid];
    s_ma[tid] = Wa[tid];
    if (tid >= 288 && tid < 416) {
        int q = tid - 288;                       // one (c,t,k) each
        int c = q >> 5, t = (q >> 2) & 7, k = q & 3;
        const float* wpp = Wp + c*128 + t*16 + k;
        float m0 = wpp[0], m1 = wpp[4], m2 = wpp[8], m3 = wpp[12];
        float inv = rsqrtf(fmaxf(m0*m0 + m1*m1 + m2*m2 + m3*m3, 1e-12f));
        float* d = s_mp + (c*8 + t)*16 + k;
        d[0] = m0*inv; d[4] = m1*inv; d[8] = m2*inv; d[12] = m3*inv;
        const float* wap = Wa + c*128 + t*16 + k;
        s_bb[(c*8 + t)*4 + k] = ba[c*8 + t] * (wap[0] + wap[4] + wap[8] + wap[12]);
    }

    // ---- x tile loader: rows h-1..h+1, cols w0-1..w0+32 at idx 3..36 ----
#pragma unroll
    for (int r3 = 0; r3 < 3; ++r3) {
        const int gr = h + r3 - 1;
        const bool ok = (gr >= 0) && (gr < 128);
#pragma unroll
        for (int it = 0; it < 2; ++it) {
            int unit = tid + it*512;              // 0..1023 = cz*8 + colgrp
            int cz   = unit >> 3;
            int col4 = (unit & 7) * 4;
            float4 v = make_float4(0.f, 0.f, 0.f, 0.f);
            if (ok)
                v = *(const float4*)(x + (((long)n*128 + cz)*128 + gr)*128 + w0 + col4);
            *(float4*)(s_x + (cz*3 + r3)*SX_STRIDE + 4 + col4) = v;
        }
    }
    if (tid < 384) {                              // halo columns
        int r3 = tid >> 7;
        int cz = tid & 127;
        int gr = h + r3 - 1;
        float vl = 0.f, vr = 0.f;
        if (gr >= 0 && gr < 128) {
            const float* row = x + (((long)n*128 + cz)*128 + gr)*128;
            if (w0 > 0)        vl = row[w0 - 1];
            if (w0 + 32 < 128) vr = row[w0 + 32];
        }
        float* sr = s_x + (cz*3 + r3)*SX_STRIDE;
        sr[3]  = vl;
        sr[36] = vr;
    }
    __syncthreads();

    // ---- Phase B: conv only. thread = (c, zq, pix), 8 z x 8 ch each ----
    {
        const int c   = tid >> 7;                 // warp-uniform
        const int zq  = (tid >> 5) & 3;           // warp-uniform
        const int pix = tid & 31;

        float w9[9][8];
#pragma unroll
        for (int p = 0; p < 9; ++p)
#pragma unroll
            for (int ch = 0; ch < 8; ++ch)
                w9[p][ch] = s_wc[(c*9 + p)*8 + ch];

#pragma unroll
        for (int zh = 0; zh < 2; ++zh) {
            float acc[8][4];
#pragma unroll
            for (int ch = 0; ch < 8; ++ch)
#pragma unroll
                for (int zz = 0; zz < 4; ++zz) acc[ch][zz] = 0.f;

#pragma unroll
            for (int zz = 0; zz < 4; ++zz) {
                const int z = zq*8 + zh*4 + zz;
                const float* xb = s_x + ((c*32 + z)*3)*SX_STRIDE + 3 + pix;
                float xv[9];
#pragma unroll
                for (int kh = 0; kh < 3; ++kh) {
                    xv[kh*3+0] = xb[kh*SX_STRIDE + 0];
                    xv[kh*3+1] = xb[kh*SX_STRIDE + 1];
                    xv[kh*3+2] = xb[kh*SX_STRIDE + 2];
                }
#pragma unroll
                for (int p = 0; p < 9; ++p)
#pragma unroll
                    for (int ch = 0; ch < 8; ++ch)
                        acc[ch][zz] = fmaf(xv[p], w9[p][ch], acc[ch][zz]);
            }
#pragma unroll
            for (int ch = 0; ch < 8; ++ch)
                *(float4*)(s_cv + ((c*8 + ch)*32 + pix)*CV_PSTR + zq*8 + zh*4) =
                    make_float4(acc[ch][0], acc[ch][1], acc[ch][2], acc[ch][3]);
        }
    }
    __syncthreads();

    // ---- Phase C: u_hat matmul in regs + routing. thread = (s, t, pix) ----
    {
        const int s   = tid >> 8;                 // warp-uniform
        const int t   = (tid >> 5) & 7;           // warp-uniform
        const int pix = tid & 31;
        const int t1  = (t >> 1) + (s ? 4 : 0);   // conv channel
        const int zb  = (t & 1) << 4;

        float u[4][16];

#pragma unroll
        for (int c = 0; c < 4; ++c) {
            const float* cb = s_cv + ((c*8 + t1)*32 + pix)*CV_PSTR + zb;
            float4 g0 = *(const float4*)(cb + 0);
            float4 g1 = *(const float4*)(cb + 4);
            float4 g2 = *(const float4*)(cb + 8);
            float4 g3 = *(const float4*)(cb + 12);
            float cp[16] = { g0.x,g0.y,g0.z,g0.w,  g1.x,g1.y,g1.z,g1.w,
                             g2.x,g2.y,g2.z,g2.w,  g3.x,g3.y,g3.z,g3.w };
            if (s == 0) {
                const float wcd = (float)(w0 + pix) * (1.0f/128.0f);
                const float hcd = (float)h * (1.0f/128.0f);
                const float* mp = s_mp + (c*8 + t)*16;
#pragma unroll
                for (int i = 0; i < 4; ++i) {
                    float p0 = cp[4*i+0], p1 = cp[4*i+1];
                    float p2 = cp[4*i+2], p3 = cp[4*i+3];
#pragma unroll
                    for (int k = 0; k < 4; ++k) {
                        float uv = p0*mp[k] + p1*mp[4+k] + p2*mp[8+k] + p3*mp[12+k];
                        if (k == 0) uv += p3 * wcd;
                        if (k == 1) uv += p3 * hcd;
                        u[c][i*4+k] = uv;
                    }
                }
            } else {
                const float* ma = s_ma + (c*8 + t)*16;
                const float* bb = s_bb + (c*8 + t)*4;
#pragma unroll
                for (int i = 0; i < 4; ++i) {
                    float a0 = cp[4*i+0], a1 = cp[4*i+1];
                    float a2 = cp[4*i+2], a3 = cp[4*i+3];
#pragma unroll
                    for (int k = 0; k < 4; ++k)
                        u[c][i*4+k] = bb[k] + a0*ma[k] + a1*ma[4+k]
                                            + a2*ma[8+k] + a3*ma[12+k];
                }
            }
        }

        float b0 = 0.f, b1 = 0.f, b2 = 0.f, b3 = 0.f;
        float p[16];

#pragma unroll
        for (int it = 0; it < 3; ++it) {
            float r0 = sigf(b0), r1 = sigf(b1), r2 = sigf(b2), r3 = sigf(b3);
#pragma unroll
            for (int zl = 0; zl < 16; ++zl)
                p[zl] = u[0][zl]*r0 + u[1][zl]*r1 + u[2][zl]*r2 + u[3][zl]*r3;
            if (s == 0) {                         // psquash over z<16
                float m = 0.f;
#pragma unroll
                for (int zl = 0; zl < 16; ++zl) m = fmaxf(m, fabsf(p[zl]));
                float inv = 1.0f / m;
#pragma unroll
                for (int zl = 0; zl < 16; ++zl) p[zl] *= inv;
            } else {                              // matwo squash over z>=16
                float sq = 0.f;
#pragma unroll
                for (int zl = 0; zl < 16; ++zl) sq = fmaf(p[zl], p[zl], sq);
                float sc = sq / (1.0f + sq) * rsqrtf(sq + 1e-9f);
#pragma unroll
                for (int zl = 0; zl < 16; ++zl) p[zl] *= sc;
            }
            if (it == 2) break;                   // last pass: p holds v

            float q0 = 0.f, q1 = 0.f, q2 = 0.f, q3 = 0.f;
#pragma unroll
            for (int zl = 0; zl < 16; ++zl) {
                q0 = fmaf(u[0][zl], p[zl], q0);
                q1 = fmaf(u[1][zl], p[zl], q1);
                q2 = fmaf(u[2][zl], p[zl], q2);
                q3 = fmaf(u[3][zl], p[zl], q3);
            }
            // double-buffered float4 exchange: 1 barrier per iteration
            float4* exw = (float4*)(s_ex + it*2048) + tid;
            const float4* exr = (float4*)(s_ex + it*2048) + (tid ^ 256);
            *exw = make_float4(q0, q1, q2, q3);
            __syncthreads();
            float4 o = *exr;
            b0 += q0 * o.x;
            b1 += q1 * o.y;
            b2 += q2 * o.z;
            b3 += q3 * o.w;
        }

        // out[n][t][z][h][w]
        float* ob = out + ((long)(n*8 + t)*32 + s*16)*16384 + h*128 + w0 + pix;
#pragma unroll
        for (int zl = 0; zl < 16; ++zl)
            ob[(long)zl*16384] = p[zl];
    }
}

extern "C" void kernel_launch(void* const* d_in, const int* in_sizes, int n_in,
                              void* d_out, int out_size)
{
    const float* x  = (const float*)d_in[0];
    const float* Wc = (const float*)d_in[1];
    const float* Wp = (const float*)d_in[2];
    const float* Wa = (const float*)d_in[3];
    const float* ba = (const float*)d_in[4];
    float* out = (float*)d_out;

    cudaFuncSetAttribute(caps_kernel,
                         cudaFuncAttributeMaxDynamicSharedMemorySize,
                         SMEM_BYTES);

    dim3 grid(4, 128, 2);   // (w/32, h, n)
    caps_kernel<<<grid, 512, SMEM_BYTES>>>(x, Wc, Wp, Wa, ba, out);
}